// round 2
// baseline (speedup 1.0000x reference)
#include <cuda_runtime.h>
#include <cuda_bf16.h>
#include <math.h>

#define BB   4
#define TIN  16
#define OC3  48
#define DD   31
#define HH   128
#define WW   128
#define HWSZ 16384
#define MCH  496    // 16*31 combined channels
#define NCH  31     // attention channels (c' = m>>4)

// ---------------- scratch (device globals: no allocations allowed) ----------
__device__ float g_q[(size_t)BB * MCH * HWSZ];
__device__ float g_k[(size_t)BB * MCH * HWSZ];
__device__ float g_v[(size_t)BB * MCH * HWSZ];
__device__ float g_sqk[BB * NCH * NCH];
__device__ float g_nq[BB * NCH];
__device__ float g_nk[BB * NCH];
__device__ float g_attn[BB * NCH * NCH];

// ---------------- K0: zero accumulators (must run every graph replay) -------
__global__ void k0_zero() {
    int i = threadIdx.x + blockIdx.x * blockDim.x;
    if (i < BB * NCH * NCH) g_sqk[i] = 0.f;
    if (i < BB * NCH) { g_nq[i] = 0.f; g_nk[i] = 0.f; }
}

// ---------------- K1: fused pointwise QKV (1x1x1) + depthwise 3x3 -----------
// grid: (16 tiles of 32x32, 124 = b*31+d), 256 threads
#define TILE 32
#define HALO 34
#define HALO2 (HALO*HALO)            // 1156
#define SMEM1 ((TIN*HALO2 + HALO2) * 4)

__global__ void k1_qkv(const float* __restrict__ x,
                       const float* __restrict__ wqkv,
                       const float* __restrict__ wdw) {
    extern __shared__ float sm1[];
    float* xs  = sm1;                 // [16][1156]
    float* pws = sm1 + TIN * HALO2;   // [1156]
    __shared__ float wq_s[OC3 * TIN];
    __shared__ float wd_s[OC3 * 9];

    const int tid = threadIdx.x;
    const int bd = blockIdx.y;
    const int b = bd / DD, d = bd - b * DD;
    const int tile = blockIdx.x;
    const int h0 = (tile >> 2) * TILE, w0 = (tile & 3) * TILE;

    for (int i = tid; i < OC3 * TIN; i += 256) wq_s[i] = wqkv[i];
    for (int i = tid; i < OC3 * 9;  i += 256) wd_s[i] = wdw[i];

    // load halo tile for all 16 input channels (zero spatial padding)
    for (int idx = tid; idx < TIN * HALO2; idx += 256) {
        int i = idx / HALO2;
        int rem = idx - i * HALO2;
        int y = rem / HALO, xx = rem - y * HALO;
        int gh = h0 + y - 1, gw = w0 + xx - 1;
        float v = 0.f;
        if (gh >= 0 && gh < HH && gw >= 0 && gw < WW)
            v = x[((size_t)(b * TIN + i) * DD + d) * HWSZ + gh * WW + gw];
        xs[idx] = v;
    }
    __syncthreads();

    for (int oc = 0; oc < OC3; oc++) {
        // pointwise into pws over the 34x34 halo grid (float2 pairs)
        float w[16];
#pragma unroll
        for (int i = 0; i < 16; i++) w[i] = wq_s[oc * 16 + i];
        for (int p2 = tid; p2 < HALO2 / 2; p2 += 256) {
            int px = p2 * 2;
            float ax = 0.f, ay = 0.f;
#pragma unroll
            for (int i = 0; i < 16; i++) {
                float2 xv = *reinterpret_cast<const float2*>(&xs[i * HALO2 + px]);
                ax += w[i] * xv.x;
                ay += w[i] * xv.y;
            }
            float2 o; o.x = ax; o.y = ay;
            *reinterpret_cast<float2*>(&pws[px]) = o;
        }
        __syncthreads();

        // depthwise 3x3 (cross-correlation) + store
        float wd[9];
#pragma unroll
        for (int i = 0; i < 9; i++) wd[i] = wd_s[oc * 9 + i];

        for (int p2 = tid; p2 < (TILE * TILE) / 2; p2 += 256) {
            int px = p2 * 2;
            int y = px >> 5, xx = px & 31;
            float o0 = 0.f, o1 = 0.f;
#pragma unroll
            for (int dy = 0; dy < 3; dy++) {
                const float* row = &pws[(y + dy) * HALO + xx];
                float2 a  = *reinterpret_cast<const float2*>(row);
                float2 b2 = *reinterpret_cast<const float2*>(row + 2);
                o0 += wd[dy * 3 + 0] * a.x  + wd[dy * 3 + 1] * a.y  + wd[dy * 3 + 2] * b2.x;
                o1 += wd[dy * 3 + 0] * a.y  + wd[dy * 3 + 1] * b2.x + wd[dy * 3 + 2] * b2.y;
            }
            int hw = (h0 + y) * WW + (w0 + xx);
            float* dst; int m;
            if (oc < 16)      { dst = g_q; m = oc * DD + d; }
            else if (oc < 32) { dst = g_k; m = (oc - 16) * DD + d; }
            else              { dst = g_v; m = (oc - 32) * DD + d; }
            float2 o; o.x = o0; o.y = o1;
            *reinterpret_cast<float2*>(&dst[((size_t)b * MCH + m) * HWSZ + hw]) = o;
        }
        __syncthreads();
    }
}

// ---------------- K2: Gram matrix Sqk + sum-of-squares norms ----------------
// Sqk[c1][c2] = sum_r sum_hw Qf[16*c1+r] * Kf[16*c2+r]
// grid: (64 hw-chunks of 256 px, 4 batches), 256 threads = 8(tc1) x 8(tc2) x 4(kg)
#define QPITCH 257
#define SMEM2 ((2 * 32 * QPITCH + 32 * 32 + 64) * 4)

__global__ void k2_gram() {
    extern __shared__ float sm2[];
    float* qs  = sm2;                       // [32][257]
    float* ks  = qs + 32 * QPITCH;          // [32][257]
    float* Cs  = ks + 32 * QPITCH;          // [32][32]
    float* nqs = Cs + 32 * 32;              // [32]
    float* nks = nqs + 32;                  // [32]

    const int tid = threadIdx.x;
    const int kg  = tid & 3;
    const int tc2 = (tid >> 2) & 7;
    const int tc1 = tid >> 5;
    const int b = blockIdx.y;
    const int hw0 = blockIdx.x * 256;

    for (int i = tid; i < 32 * 32; i += 256) Cs[i] = 0.f;
    if (tid < 32) { nqs[tid] = 0.f; nks[tid] = 0.f; }

    float accC[16];
#pragma unroll
    for (int i = 0; i < 16; i++) accC[i] = 0.f;
    float accNq[4] = {0.f, 0.f, 0.f, 0.f};
    float accNk[4] = {0.f, 0.f, 0.f, 0.f};
    const bool diag = (tc1 == tc2);

    for (int r = 0; r < 16; r++) {
        for (int idx = tid; idx < 32 * 256; idx += 256) {
            int c = idx >> 8, p = idx & 255;
            float qv = 0.f, kv = 0.f;
            if (c < 31) {
                size_t off = ((size_t)b * MCH + (16 * c + r)) * HWSZ + hw0 + p;
                qv = g_q[off];
                kv = g_k[off];
            }
            qs[c * QPITCH + p] = qv;
            ks[c * QPITCH + p] = kv;
        }
        __syncthreads();

        for (int j = 0; j < 64; j++) {
            int p = kg + 4 * j;
            float qv[4], kv[4];
#pragma unroll
            for (int a = 0; a < 4; a++) {
                qv[a] = qs[(tc1 * 4 + a) * QPITCH + p];
                kv[a] = ks[(tc2 * 4 + a) * QPITCH + p];
            }
#pragma unroll
            for (int a = 0; a < 4; a++)
#pragma unroll
                for (int c = 0; c < 4; c++)
                    accC[a * 4 + c] += qv[a] * kv[c];
            if (diag) {
#pragma unroll
                for (int a = 0; a < 4; a++) {
                    accNq[a] += qv[a] * qv[a];
                    accNk[a] += kv[a] * kv[a];
                }
            }
        }
        __syncthreads();
    }

#pragma unroll
    for (int a = 0; a < 4; a++)
#pragma unroll
        for (int c = 0; c < 4; c++)
            atomicAdd(&Cs[(tc1 * 4 + a) * 32 + (tc2 * 4 + c)], accC[a * 4 + c]);
    if (diag) {
#pragma unroll
        for (int a = 0; a < 4; a++) {
            atomicAdd(&nqs[tc1 * 4 + a], accNq[a]);
            atomicAdd(&nks[tc1 * 4 + a], accNk[a]);
        }
    }
    __syncthreads();

    for (int idx = tid; idx < NCH * NCH; idx += 256) {
        int c1 = idx / NCH, c2 = idx - c1 * NCH;
        atomicAdd(&g_sqk[b * NCH * NCH + idx], Cs[c1 * 32 + c2]);
    }
    if (tid < NCH) {
        atomicAdd(&g_nq[b * NCH + tid], nqs[tid]);
        atomicAdd(&g_nk[b * NCH + tid], nks[tid]);
    }
}

// ---------------- K3: softmax over 4 x 31 x 31 -------------------------------
__global__ void k3_softmax(const float* __restrict__ temperature) {
    int warp = threadIdx.x >> 5, lane = threadIdx.x & 31;
    int b = warp;                       // 4 warps, one per batch
    float temp = temperature[0];
    for (int c1 = 0; c1 < NCH; c1++) {
        float nq = fmaxf(sqrtf(g_nq[b * NCH + c1]), 1e-12f);
        float logit = -1e30f;
        if (lane < NCH) {
            float nk = fmaxf(sqrtf(g_nk[b * NCH + lane]), 1e-12f);
            logit = g_sqk[(b * NCH + c1) * NCH + lane] / (nq * nk) * temp;
        }
        float mx = logit;
#pragma unroll
        for (int s = 16; s; s >>= 1) mx = fmaxf(mx, __shfl_xor_sync(0xffffffff, mx, s));
        float e = (lane < NCH) ? expf(logit - mx) : 0.f;
        float sum = e;
#pragma unroll
        for (int s = 16; s; s >>= 1) sum += __shfl_xor_sync(0xffffffff, sum, s);
        if (lane < NCH) g_attn[(b * NCH + c1) * NCH + lane] = e / sum;
    }
}

// ---------------- K4: out = attn @ V, then 16x16 projection ------------------
// grid: (1024 pixel-chunks of 16, 4 batches), 256 threads
#define PIX4 16
#define VPITCH 20
#define SMEM4 ((2 * MCH * VPITCH + NCH * NCH + 256) * 4)

__global__ void k4_out(const float* __restrict__ wproj, float* __restrict__ out) {
    extern __shared__ float sm4[];
    float* vs     = sm4;                        // [496][20]
    float* oas    = vs + MCH * VPITCH;          // [496][20]
    float* attn_s = oas + MCH * VPITCH;         // [961]
    float* wp_s   = attn_s + NCH * NCH;         // [256]

    const int tid = threadIdx.x;
    const int b = blockIdx.y;
    const int hw0 = blockIdx.x * PIX4;

    for (int i = tid; i < NCH * NCH; i += 256) attn_s[i] = g_attn[b * NCH * NCH + i];
    if (tid < 256) wp_s[tid] = wproj[tid];
    for (int idx = tid; idx < MCH * PIX4; idx += 256) {
        int m = idx >> 4, px = idx & 15;
        vs[m * VPITCH + px] = g_v[((size_t)b * MCH + m) * HWSZ + hw0 + px];
    }
    __syncthreads();

    // stage 1: oa[m][px] = sum_dc attn[m>>4][dc] * v[16*dc + (m&15)][px]
    for (int m = tid; m < MCH; m += 256) {
        int c1 = m >> 4, r = m & 15;
        float4 acc0 = {0,0,0,0}, acc1 = {0,0,0,0}, acc2 = {0,0,0,0}, acc3 = {0,0,0,0};
        for (int dc = 0; dc < NCH; dc++) {
            float a = attn_s[c1 * NCH + dc];
            const float4* vrow = reinterpret_cast<const float4*>(&vs[(16 * dc + r) * VPITCH]);
            float4 v0 = vrow[0], v1 = vrow[1], v2 = vrow[2], v3 = vrow[3];
            acc0.x += a * v0.x; acc0.y += a * v0.y; acc0.z += a * v0.z; acc0.w += a * v0.w;
            acc1.x += a * v1.x; acc1.y += a * v1.y; acc1.z += a * v1.z; acc1.w += a * v1.w;
            acc2.x += a * v2.x; acc2.y += a * v2.y; acc2.z += a * v2.z; acc2.w += a * v2.w;
            acc3.x += a * v3.x; acc3.y += a * v3.y; acc3.z += a * v3.z; acc3.w += a * v3.w;
        }
        float4* orow = reinterpret_cast<float4*>(&oas[m * VPITCH]);
        orow[0] = acc0; orow[1] = acc1; orow[2] = acc2; orow[3] = acc3;
    }
    __syncthreads();

    // stage 2: out[o*31+ds][px] = sum_i wproj[o][i] * oa[i*31+ds][px]
    for (int m = tid; m < MCH; m += 256) {
        int o = m / NCH, ds = m - o * NCH;
        float4 acc0 = {0,0,0,0}, acc1 = {0,0,0,0}, acc2 = {0,0,0,0}, acc3 = {0,0,0,0};
#pragma unroll
        for (int i = 0; i < 16; i++) {
            float wpv = wp_s[o * 16 + i];
            const float4* row = reinterpret_cast<const float4*>(&oas[(i * NCH + ds) * VPITCH]);
            float4 v0 = row[0], v1 = row[1], v2 = row[2], v3 = row[3];
            acc0.x += wpv * v0.x; acc0.y += wpv * v0.y; acc0.z += wpv * v0.z; acc0.w += wpv * v0.w;
            acc1.x += wpv * v1.x; acc1.y += wpv * v1.y; acc1.z += wpv * v1.z; acc1.w += wpv * v1.w;
            acc2.x += wpv * v2.x; acc2.y += wpv * v2.y; acc2.z += wpv * v2.z; acc2.w += wpv * v2.w;
            acc3.x += wpv * v3.x; acc3.y += wpv * v3.y; acc3.z += wpv * v3.z; acc3.w += wpv * v3.w;
        }
        float4* dst = reinterpret_cast<float4*>(
            &out[((size_t)(b * 16 + o) * DD + ds) * HWSZ + hw0]);
        dst[0] = acc0; dst[1] = acc1; dst[2] = acc2; dst[3] = acc3;
    }
}

// ---------------- launch ------------------------------------------------------
extern "C" void kernel_launch(void* const* d_in, const int* in_sizes, int n_in,
                              void* d_out, int out_size) {
    const float* x     = (const float*)d_in[0];
    const float* wqkv  = (const float*)d_in[1];
    const float* wdw   = (const float*)d_in[2];
    const float* wproj = (const float*)d_in[3];
    const float* temp  = (const float*)d_in[4];
    float* out = (float*)d_out;

    cudaFuncSetAttribute(k1_qkv,  cudaFuncAttributeMaxDynamicSharedMemorySize, SMEM1);
    cudaFuncSetAttribute(k2_gram, cudaFuncAttributeMaxDynamicSharedMemorySize, SMEM2);
    cudaFuncSetAttribute(k4_out,  cudaFuncAttributeMaxDynamicSharedMemorySize, SMEM4);

    k0_zero<<<16, 256>>>();

    dim3 g1(16, BB * DD);
    k1_qkv<<<g1, 256, SMEM1>>>(x, wqkv, wdw);

    dim3 g2(64, BB);
    k2_gram<<<g2, 256, SMEM2>>>();

    k3_softmax<<<1, 128>>>(temp);

    dim3 g4(HWSZ / PIX4, BB);
    k4_out<<<g4, 256, SMEM4>>>(wproj, out);
}

// round 4
// speedup vs baseline: 1.8205x; 1.8205x over previous
#include <cuda_runtime.h>
#include <cuda_bf16.h>
#include <math.h>

#define BB   4
#define TIN  16
#define OC3  48
#define DD   31
#define HH   128
#define WW   128
#define HWSZ 16384
#define MCH  496    // 16*31 combined channels
#define NCH  31     // attention channels

typedef unsigned long long u64;

__device__ __forceinline__ u64 pack2(float x, float y) {
    u64 r; asm("mov.b64 %0, {%1, %2};" : "=l"(r) : "f"(x), "f"(y)); return r;
}
__device__ __forceinline__ float2 unpack2(u64 v) {
    float2 r; asm("mov.b64 {%0, %1}, %2;" : "=f"(r.x), "=f"(r.y) : "l"(v)); return r;
}
__device__ __forceinline__ void fma2(u64& d, u64 a, u64 b) {
    asm("fma.rn.f32x2 %0, %1, %2, %0;" : "+l"(d) : "l"(a), "l"(b));
}

// ---------------- scratch --------------------------------------------------
__device__ float g_q[(size_t)BB * MCH * HWSZ];
__device__ float g_k[(size_t)BB * MCH * HWSZ];
__device__ float g_v[(size_t)BB * MCH * HWSZ];
__device__ float g_sqk[BB * NCH * NCH];
__device__ float g_nq[BB * NCH];
__device__ float g_nk[BB * NCH];
__device__ float g_attn[BB * NCH * NCH];

// ---------------- K0: zero accumulators ------------------------------------
__global__ void k0_zero() {
    int i = threadIdx.x + blockIdx.x * blockDim.x;
    if (i < BB * NCH * NCH) g_sqk[i] = 0.f;
    if (i < BB * NCH) { g_nq[i] = 0.f; g_nk[i] = 0.f; }
}

// ---------------- K1: fused pointwise QKV + depthwise 3x3 ------------------
// tile 32 wide x 16 tall. Halo: cols [w0-2, w0+34) = 36 (18 ALIGNED pairs),
// rows [h0-1, h0+17) = 18. 324 pairs total; 256 threads, 68 take a 2nd slot.
#define HLW 36
#define NPAIR 324

__device__ __forceinline__ void k1_load_slot(u64* xr, int pp, int b, int d,
                                             int h0, int w0, const float* __restrict__ x) {
    int y = pp / 18;
    int px = pp - y * 18;
    int gh = h0 + y - 1;
    int gw0 = w0 + 2 * px - 2;            // even -> 8B-aligned pairs
    if (gh >= 0 && gh < HH && gw0 >= 0 && gw0 < WW - 1) {
        const float* xp = x + ((size_t)(b * TIN) * DD + d) * HWSZ + gh * WW + gw0;
#pragma unroll
        for (int i = 0; i < 16; i++) { xr[i] = *(const u64*)xp; xp += DD * HWSZ; }
    } else {
#pragma unroll
        for (int i = 0; i < 16; i++) xr[i] = 0ULL;
    }
}

__global__ void __launch_bounds__(256, 2)
k1_qkv(const float* __restrict__ x, const float* __restrict__ wqkv,
       const float* __restrict__ wdw) {
    __shared__ float2 wq2[OC3][16];
    __shared__ float2 wd2[OC3][9];
    __shared__ __align__(16) float pws[2][HLW * 18];   // 648 each

    const int tid = threadIdx.x;
    const int bd = blockIdx.y;
    const int b = bd / DD, d = bd - b * DD;
    const int tx = blockIdx.x & 3, ty = blockIdx.x >> 2;
    const int h0 = ty * 16, w0 = tx * 32;

    for (int i = tid; i < OC3 * 16; i += 256) {
        float w = wqkv[i]; wq2[i >> 4][i & 15] = make_float2(w, w);
    }
    for (int i = tid; i < OC3 * 9; i += 256) {
        float w = wdw[i]; wd2[i / 9][i % 9] = make_float2(w, w);
    }

    u64 xr0[16], xr1[16];
    k1_load_slot(xr0, tid, b, d, h0, w0, x);
    const bool slot1 = (tid < NPAIR - 256);
    if (slot1) k1_load_slot(xr1, tid + 256, b, d, h0, w0, x);

    const int oy = tid >> 4;
    const int ox = (tid & 15) * 2;

    __syncthreads();

    for (int oc = 0; oc < OC3; oc++) {
        float* pwb = pws[oc & 1];
        // pointwise from registers
        {
            u64 acc = 0ULL;
#pragma unroll
            for (int i = 0; i < 16; i++) fma2(acc, xr0[i], *(const u64*)&wq2[oc][i]);
            *(u64*)&pwb[2 * tid] = acc;
            if (slot1) {
                u64 acc1 = 0ULL;
#pragma unroll
                for (int i = 0; i < 16; i++) fma2(acc1, xr1[i], *(const u64*)&wq2[oc][i]);
                *(u64*)&pwb[2 * (tid + 256)] = acc1;
            }
        }
        __syncthreads();
        // depthwise 3x3: taps at halo cols ox+1..ox+4 (halo col0 = w0-2)
        u64 acc = 0ULL;
#pragma unroll
        for (int dy = 0; dy < 3; dy++) {
            const float* row = pwb + (oy + dy) * HLW + ox;
            u64 av = *(const u64*)row;          // hx ox,   ox+1
            u64 bv = *(const u64*)(row + 2);    // hx ox+2, ox+3
            u64 cv = *(const u64*)(row + 4);    // hx ox+4, ox+5
            u64 mv1 = (av >> 32) | (bv << 32);  // hx ox+1, ox+2  (left tap)
            u64 mv2 = (bv >> 32) | (cv << 32);  // hx ox+3, ox+4  (right tap)
            fma2(acc, mv1, *(const u64*)&wd2[oc][3 * dy + 0]);
            fma2(acc, bv,  *(const u64*)&wd2[oc][3 * dy + 1]);
            fma2(acc, mv2, *(const u64*)&wd2[oc][3 * dy + 2]);
        }
        float* dst; int m;
        if (oc < 16)      { dst = g_q; m = oc * DD + d; }
        else if (oc < 32) { dst = g_k; m = (oc - 16) * DD + d; }
        else              { dst = g_v; m = (oc - 32) * DD + d; }
        *(u64*)&dst[((size_t)(b * MCH) + m) * HWSZ + (h0 + oy) * WW + w0 + ox] = acc;
        // no second barrier: double-buffered pws
    }
}

// ---------------- K2: Gram matrix + norms ----------------------------------
// 256 blocks (64 px-chunks x 4 batches). 256 threads: kg(8) x tc2(8) x tc1(4).
#define K2PITCH 260
#define SMEM2 (2 * 32 * K2PITCH * 4)

__global__ void __launch_bounds__(256, 2) k2_gram() {
    extern __shared__ float sm2[];
    float* qs = sm2;                    // [32][260]
    float* ks = sm2 + 32 * K2PITCH;     // [32][260]

    const int tid = threadIdx.x;
    const int kg  = tid & 7;
    const int tc2 = (tid >> 3) & 7;
    const int tc1 = tid >> 6;
    const int b = blockIdx.y;
    const int hw0 = blockIdx.x * 256;

    const int lrow = tid >> 3;
    const int lc8  = tid & 7;

    u64 acc[32];
#pragma unroll
    for (int i = 0; i < 32; i++) acc[i] = 0ULL;
    float nq_acc = 0.f, nk_acc = 0.f;

    for (int r = 0; r < 16; r++) {
        if (r) __syncthreads();
        {
            const bool valid = (lrow < NCH);
            size_t goff = ((size_t)(b * MCH) + 16 * lrow + r) * HWSZ + hw0;
#pragma unroll
            for (int kk = 0; kk < 8; kk++) {
                int f4 = lc8 + 8 * kk;
                float4 qv = make_float4(0.f, 0.f, 0.f, 0.f);
                float4 kv = make_float4(0.f, 0.f, 0.f, 0.f);
                if (valid) {
                    qv = *(const float4*)&g_q[goff + 4 * f4];
                    kv = *(const float4*)&g_k[goff + 4 * f4];
                }
                *(float4*)&qs[lrow * K2PITCH + 4 * f4] = qv;
                *(float4*)&ks[lrow * K2PITCH + 4 * f4] = kv;
                nq_acc += qv.x * qv.x + qv.y * qv.y + qv.z * qv.z + qv.w * qv.w;
                nk_acc += kv.x * kv.x + kv.y * kv.y + kv.z * kv.z + kv.w * kv.w;
            }
        }
        __syncthreads();
        for (int jj = 0; jj < 16; jj++) {
            int px = 2 * kg + 16 * jj;
            u64 qa[8], kv[4];
#pragma unroll
            for (int a = 0; a < 8; a++) qa[a] = *(const u64*)&qs[(tc1 * 8 + a) * K2PITCH + px];
#pragma unroll
            for (int c = 0; c < 4; c++) kv[c] = *(const u64*)&ks[(tc2 * 4 + c) * K2PITCH + px];
#pragma unroll
            for (int a = 0; a < 8; a++)
#pragma unroll
                for (int c = 0; c < 4; c++)
                    fma2(acc[a * 4 + c], qa[a], kv[c]);
        }
    }

    nq_acc += __shfl_xor_sync(0xffffffffu, nq_acc, 1);
    nq_acc += __shfl_xor_sync(0xffffffffu, nq_acc, 2);
    nq_acc += __shfl_xor_sync(0xffffffffu, nq_acc, 4);
    nk_acc += __shfl_xor_sync(0xffffffffu, nk_acc, 1);
    nk_acc += __shfl_xor_sync(0xffffffffu, nk_acc, 2);
    nk_acc += __shfl_xor_sync(0xffffffffu, nk_acc, 4);
    if (lc8 == 0 && lrow < NCH) {
        atomicAdd(&g_nq[b * NCH + lrow], nq_acc);
        atomicAdd(&g_nk[b * NCH + lrow], nk_acc);
    }

#pragma unroll
    for (int e = 0; e < 32; e++) {
        float2 f = unpack2(acc[e]);
        float s = f.x + f.y;
        s += __shfl_xor_sync(0xffffffffu, s, 1);
        s += __shfl_xor_sync(0xffffffffu, s, 2);
        s += __shfl_xor_sync(0xffffffffu, s, 4);
        if (kg == 0) {
            int row = tc1 * 8 + (e >> 2);
            int col = tc2 * 4 + (e & 3);
            if (row < NCH && col < NCH)
                atomicAdd(&g_sqk[b * NCH * NCH + row * NCH + col], s);
        }
    }
}

// ---------------- K3: softmax (one block per output row) --------------------
__global__ void k3_softmax(const float* __restrict__ temperature) {
    const int b = blockIdx.y, c1 = blockIdx.x, lane = threadIdx.x;
    const float temp = temperature[0];
    float nq = fmaxf(sqrtf(g_nq[b * NCH + c1]), 1e-12f);
    float logit = -1e30f;
    if (lane < NCH) {
        float nk = fmaxf(sqrtf(g_nk[b * NCH + lane]), 1e-12f);
        logit = g_sqk[(b * NCH + c1) * NCH + lane] / (nq * nk) * temp;
    }
    float mx = logit;
#pragma unroll
    for (int s = 16; s; s >>= 1) mx = fmaxf(mx, __shfl_xor_sync(0xffffffffu, mx, s));
    float e = (lane < NCH) ? expf(logit - mx) : 0.f;
    float sum = e;
#pragma unroll
    for (int s = 16; s; s >>= 1) sum += __shfl_xor_sync(0xffffffffu, sum, s);
    if (lane < NCH) g_attn[(b * NCH + c1) * NCH + lane] = e / sum;
}

// ---------------- K4: out = attn @ V then 16x16 projection ------------------
#define OAPITCH 32
#define SMEM4 ((MCH * OAPITCH) * 4 + (NCH * 32) * 8 + 256 * 4)

__global__ void __launch_bounds__(256, 2)
k4_out(const float* __restrict__ wproj, float* __restrict__ out) {
    extern __shared__ float sm4[];
    float* oa = sm4;                                  // [496][32]
    float2* attn2 = (float2*)(sm4 + MCH * OAPITCH);   // [31][32] dup pairs
    float* wp_s = sm4 + MCH * OAPITCH + NCH * 32 * 2; // [256]

    const int tid = threadIdx.x;
    const int b = blockIdx.y;
    const int hw0 = blockIdx.x * 32;

    for (int i = tid; i < NCH * NCH; i += 256) {
        int c1 = i / NCH, dc = i - c1 * NCH;
        float a = g_attn[b * NCH * NCH + i];
        attn2[c1 * 32 + dc] = make_float2(a, a);
    }
    wp_s[tid] = wproj[tid];
    __syncthreads();

    // ---- stage 1: oa[16c+r][px] = sum_dc attn[c][dc] * v[16dc+r][px]
    {
        const int pxp = tid & 15, r = tid >> 4;
        const float* vbase = g_v + ((size_t)(b * MCH) + r) * HWSZ + hw0 + 2 * pxp;
        u64 acc[31];
#pragma unroll
        for (int c = 0; c < 31; c++) acc[c] = 0ULL;

        u64 v0 = *(const u64*)(vbase);
        u64 v1 = *(const u64*)(vbase + 16 * HWSZ);
        for (int j = 0; j < 15; j++) {
            int dc = 2 * j;
            u64 n0 = 0ULL, n1 = 0ULL;
            if (j < 14) {
                n0 = *(const u64*)(vbase + (size_t)16 * (dc + 2) * HWSZ);
                n1 = *(const u64*)(vbase + (size_t)16 * (dc + 3) * HWSZ);
            } else {
                n0 = *(const u64*)(vbase + (size_t)16 * 30 * HWSZ);
            }
#pragma unroll
            for (int c = 0; c < 31; c++) {
                ulonglong2 at = *(const ulonglong2*)&attn2[c * 32 + dc];
                fma2(acc[c], v0, at.x);
                fma2(acc[c], v1, at.y);
            }
            v0 = n0; v1 = n1;
        }
#pragma unroll
        for (int c = 0; c < 31; c++) {
            u64 a30 = *(const u64*)&attn2[c * 32 + 30];
            fma2(acc[c], v0, a30);
        }
#pragma unroll
        for (int c = 0; c < 31; c++)
            *(u64*)&oa[(16 * c + r) * OAPITCH + 2 * pxp] = acc[c];
    }
    __syncthreads();

    // ---- stage 2: out[o*31+ds][px] = sum_i wp[o][i] * oa[i*31+ds][px]
    {
        const int pxp = tid & 15;
        const int oo = (tid >> 4) & 7;
        const int dsg = tid >> 7;
        const int o0 = 2 * oo, o1 = 2 * oo + 1;
        u64 wpa[16], wpb[16];
#pragma unroll
        for (int i = 0; i < 16; i++) {
            float wa = wp_s[o0 * 16 + i], wb = wp_s[o1 * 16 + i];
            wpa[i] = pack2(wa, wa);
            wpb[i] = pack2(wb, wb);
        }
        for (int ds = dsg; ds < NCH; ds += 2) {
            u64 a0 = 0ULL, a1 = 0ULL;
#pragma unroll
            for (int i = 0; i < 16; i++) {
                u64 ov = *(const u64*)&oa[(i * NCH + ds) * OAPITCH + 2 * pxp];
                fma2(a0, ov, wpa[i]);
                fma2(a1, ov, wpb[i]);
            }
            size_t obase = ((size_t)((b * 16 + o0) * DD + ds)) * HWSZ + hw0 + 2 * pxp;
            *(u64*)&out[obase] = a0;
            *(u64*)&out[obase + (size_t)DD * HWSZ] = a1;
        }
    }
}

// ---------------- launch -----------------------------------------------------
extern "C" void kernel_launch(void* const* d_in, const int* in_sizes, int n_in,
                              void* d_out, int out_size) {
    const float* x     = (const float*)d_in[0];
    const float* wqkv  = (const float*)d_in[1];
    const float* wdw   = (const float*)d_in[2];
    const float* wproj = (const float*)d_in[3];
    const float* temp  = (const float*)d_in[4];
    float* out = (float*)d_out;

    cudaFuncSetAttribute(k2_gram, cudaFuncAttributeMaxDynamicSharedMemorySize, SMEM2);
    cudaFuncSetAttribute(k4_out,  cudaFuncAttributeMaxDynamicSharedMemorySize, SMEM4);

    k0_zero<<<16, 256>>>();

    dim3 g1(32, BB * DD);
    k1_qkv<<<g1, 256>>>(x, wqkv, wdw);

    dim3 g2(64, BB);
    k2_gram<<<g2, 256, SMEM2>>>();

    dim3 g3(NCH, BB);
    k3_softmax<<<g3, 32>>>(temp);

    dim3 g4(HWSZ / 32, BB);
    k4_out<<<g4, 256, SMEM4>>>(wproj, out);
}

// round 5
// speedup vs baseline: 1.8337x; 1.0073x over previous
#include <cuda_runtime.h>
#include <cuda_bf16.h>
#include <math.h>

#define BB   4
#define TIN  16
#define OC3  48
#define DD   31
#define HH   128
#define WW   128
#define HWSZ 16384
#define MCH  496    // 16*31 combined channels
#define NCH  31     // attention channels

typedef unsigned long long u64;

__device__ __forceinline__ u64 pack2(float x, float y) {
    u64 r; asm("mov.b64 %0, {%1, %2};" : "=l"(r) : "f"(x), "f"(y)); return r;
}
__device__ __forceinline__ float2 unpack2(u64 v) {
    float2 r; asm("mov.b64 {%0, %1}, %2;" : "=f"(r.x), "=f"(r.y) : "l"(v)); return r;
}
__device__ __forceinline__ void fma2(u64& d, u64 a, u64 b) {
    asm("fma.rn.f32x2 %0, %1, %2, %0;" : "+l"(d) : "l"(a), "l"(b));
}

// ---------------- scratch --------------------------------------------------
__device__ float g_q[(size_t)BB * MCH * HWSZ];
__device__ float g_k[(size_t)BB * MCH * HWSZ];
__device__ float g_v[(size_t)BB * MCH * HWSZ];
__device__ float g_sqk[BB * NCH * NCH];
__device__ float g_nq[BB * NCH];
__device__ float g_nk[BB * NCH];
__device__ float g_attn[BB * NCH * NCH];

// ---------------- K0: zero accumulators ------------------------------------
__global__ void k0_zero() {
    int i = threadIdx.x + blockIdx.x * blockDim.x;
    if (i < BB * NCH * NCH) g_sqk[i] = 0.f;
    if (i < BB * NCH) { g_nq[i] = 0.f; g_nk[i] = 0.f; }
}

// ---------------- K1: fused pointwise QKV + depthwise 3x3 ------------------
// tile 32 wide x 16 tall. Halo: cols [w0-2, w0+34) = 36 (18 ALIGNED pairs),
// rows [h0-1, h0+17) = 18. 324 pairs total; 256 threads, 68 take a 2nd slot.
#define HLW 36
#define NPAIR 324

__device__ __forceinline__ void k1_load_slot(u64* xr, int pp, int b, int d,
                                             int h0, int w0, const float* __restrict__ x) {
    int y = pp / 18;
    int px = pp - y * 18;
    int gh = h0 + y - 1;
    int gw0 = w0 + 2 * px - 2;            // even -> 8B-aligned pairs
    if (gh >= 0 && gh < HH && gw0 >= 0 && gw0 < WW - 1) {
        const float* xp = x + ((size_t)(b * TIN) * DD + d) * HWSZ + gh * WW + gw0;
#pragma unroll
        for (int i = 0; i < 16; i++) { xr[i] = *(const u64*)xp; xp += DD * HWSZ; }
    } else {
#pragma unroll
        for (int i = 0; i < 16; i++) xr[i] = 0ULL;
    }
}

__global__ void __launch_bounds__(256, 2)
k1_qkv(const float* __restrict__ x, const float* __restrict__ wqkv,
       const float* __restrict__ wdw) {
    __shared__ float2 wq2[OC3][16];
    __shared__ float2 wd2[OC3][9];
    __shared__ __align__(16) float pws[2][HLW * 18];   // 648 each

    const int tid = threadIdx.x;
    const int bd = blockIdx.y;
    const int b = bd / DD, d = bd - b * DD;
    const int tx = blockIdx.x & 3, ty = blockIdx.x >> 2;
    const int h0 = ty * 16, w0 = tx * 32;

    for (int i = tid; i < OC3 * 16; i += 256) {
        float w = wqkv[i]; wq2[i >> 4][i & 15] = make_float2(w, w);
    }
    for (int i = tid; i < OC3 * 9; i += 256) {
        float w = wdw[i]; wd2[i / 9][i % 9] = make_float2(w, w);
    }

    u64 xr0[16], xr1[16];
    k1_load_slot(xr0, tid, b, d, h0, w0, x);
    const bool slot1 = (tid < NPAIR - 256);
    if (slot1) k1_load_slot(xr1, tid + 256, b, d, h0, w0, x);

    const int oy = tid >> 4;
    const int ox = (tid & 15) * 2;

    __syncthreads();

    for (int oc = 0; oc < OC3; oc++) {
        float* pwb = pws[oc & 1];
        // pointwise from registers
        {
            u64 acc = 0ULL;
#pragma unroll
            for (int i = 0; i < 16; i++) fma2(acc, xr0[i], *(const u64*)&wq2[oc][i]);
            *(u64*)&pwb[2 * tid] = acc;
            if (slot1) {
                u64 acc1 = 0ULL;
#pragma unroll
                for (int i = 0; i < 16; i++) fma2(acc1, xr1[i], *(const u64*)&wq2[oc][i]);
                *(u64*)&pwb[2 * (tid + 256)] = acc1;
            }
        }
        __syncthreads();
        // depthwise 3x3: taps at halo cols ox+1..ox+4 (halo col0 = w0-2)
        u64 acc = 0ULL;
#pragma unroll
        for (int dy = 0; dy < 3; dy++) {
            const float* row = pwb + (oy + dy) * HLW + ox;
            u64 av = *(const u64*)row;          // hx ox,   ox+1
            u64 bv = *(const u64*)(row + 2);    // hx ox+2, ox+3
            u64 cv = *(const u64*)(row + 4);    // hx ox+4, ox+5
            u64 mv1 = (av >> 32) | (bv << 32);  // hx ox+1, ox+2  (left tap)
            u64 mv2 = (bv >> 32) | (cv << 32);  // hx ox+3, ox+4  (right tap)
            fma2(acc, mv1, *(const u64*)&wd2[oc][3 * dy + 0]);
            fma2(acc, bv,  *(const u64*)&wd2[oc][3 * dy + 1]);
            fma2(acc, mv2, *(const u64*)&wd2[oc][3 * dy + 2]);
        }
        float* dst; int m;
        if (oc < 16)      { dst = g_q; m = oc * DD + d; }
        else if (oc < 32) { dst = g_k; m = (oc - 16) * DD + d; }
        else              { dst = g_v; m = (oc - 32) * DD + d; }
        *(u64*)&dst[((size_t)(b * MCH) + m) * HWSZ + (h0 + oy) * WW + w0 + ox] = acc;
        // no second barrier: double-buffered pws
    }
}

// ---------------- K2: Gram matrix + norms ----------------------------------
// 256 blocks (64 px-chunks x 4 batches). 256 threads: kg(8) x tc2(8) x tc1(4).
#define K2PITCH 260
#define SMEM2 (2 * 32 * K2PITCH * 4)

__global__ void __launch_bounds__(256, 2) k2_gram() {
    extern __shared__ float sm2[];
    float* qs = sm2;                    // [32][260]
    float* ks = sm2 + 32 * K2PITCH;     // [32][260]

    const int tid = threadIdx.x;
    const int kg  = tid & 7;
    const int tc2 = (tid >> 3) & 7;
    const int tc1 = tid >> 6;
    const int b = blockIdx.y;
    const int hw0 = blockIdx.x * 256;

    const int lrow = tid >> 3;
    const int lc8  = tid & 7;

    u64 acc[32];
#pragma unroll
    for (int i = 0; i < 32; i++) acc[i] = 0ULL;
    float nq_acc = 0.f, nk_acc = 0.f;

    for (int r = 0; r < 16; r++) {
        if (r) __syncthreads();
        {
            const bool valid = (lrow < NCH);
            size_t goff = ((size_t)(b * MCH) + 16 * lrow + r) * HWSZ + hw0;
#pragma unroll
            for (int kk = 0; kk < 8; kk++) {
                int f4 = lc8 + 8 * kk;
                float4 qv = make_float4(0.f, 0.f, 0.f, 0.f);
                float4 kv = make_float4(0.f, 0.f, 0.f, 0.f);
                if (valid) {
                    qv = *(const float4*)&g_q[goff + 4 * f4];
                    kv = *(const float4*)&g_k[goff + 4 * f4];
                }
                *(float4*)&qs[lrow * K2PITCH + 4 * f4] = qv;
                *(float4*)&ks[lrow * K2PITCH + 4 * f4] = kv;
                nq_acc += qv.x * qv.x + qv.y * qv.y + qv.z * qv.z + qv.w * qv.w;
                nk_acc += kv.x * kv.x + kv.y * kv.y + kv.z * kv.z + kv.w * kv.w;
            }
        }
        __syncthreads();
        for (int jj = 0; jj < 16; jj++) {
            int px = 2 * kg + 16 * jj;
            u64 qa[8], kv[4];
#pragma unroll
            for (int a = 0; a < 8; a++) qa[a] = *(const u64*)&qs[(tc1 * 8 + a) * K2PITCH + px];
#pragma unroll
            for (int c = 0; c < 4; c++) kv[c] = *(const u64*)&ks[(tc2 * 4 + c) * K2PITCH + px];
#pragma unroll
            for (int a = 0; a < 8; a++)
#pragma unroll
                for (int c = 0; c < 4; c++)
                    fma2(acc[a * 4 + c], qa[a], kv[c]);
        }
    }

    nq_acc += __shfl_xor_sync(0xffffffffu, nq_acc, 1);
    nq_acc += __shfl_xor_sync(0xffffffffu, nq_acc, 2);
    nq_acc += __shfl_xor_sync(0xffffffffu, nq_acc, 4);
    nk_acc += __shfl_xor_sync(0xffffffffu, nk_acc, 1);
    nk_acc += __shfl_xor_sync(0xffffffffu, nk_acc, 2);
    nk_acc += __shfl_xor_sync(0xffffffffu, nk_acc, 4);
    if (lc8 == 0 && lrow < NCH) {
        atomicAdd(&g_nq[b * NCH + lrow], nq_acc);
        atomicAdd(&g_nk[b * NCH + lrow], nk_acc);
    }

#pragma unroll
    for (int e = 0; e < 32; e++) {
        float2 f = unpack2(acc[e]);
        float s = f.x + f.y;
        s += __shfl_xor_sync(0xffffffffu, s, 1);
        s += __shfl_xor_sync(0xffffffffu, s, 2);
        s += __shfl_xor_sync(0xffffffffu, s, 4);
        if (kg == 0) {
            int row = tc1 * 8 + (e >> 2);
            int col = tc2 * 4 + (e & 3);
            if (row < NCH && col < NCH)
                atomicAdd(&g_sqk[b * NCH * NCH + row * NCH + col], s);
        }
    }
}

// ---------------- K3: softmax (one block per output row) --------------------
__global__ void k3_softmax(const float* __restrict__ temperature) {
    const int b = blockIdx.y, c1 = blockIdx.x, lane = threadIdx.x;
    const float temp = temperature[0];
    float nq = fmaxf(sqrtf(g_nq[b * NCH + c1]), 1e-12f);
    float logit = -1e30f;
    if (lane < NCH) {
        float nk = fmaxf(sqrtf(g_nk[b * NCH + lane]), 1e-12f);
        logit = g_sqk[(b * NCH + c1) * NCH + lane] / (nq * nk) * temp;
    }
    float mx = logit;
#pragma unroll
    for (int s = 16; s; s >>= 1) mx = fmaxf(mx, __shfl_xor_sync(0xffffffffu, mx, s));
    float e = (lane < NCH) ? expf(logit - mx) : 0.f;
    float sum = e;
#pragma unroll
    for (int s = 16; s; s >>= 1) sum += __shfl_xor_sync(0xffffffffu, sum, s);
    if (lane < NCH) g_attn[(b * NCH + c1) * NCH + lane] = e / sum;
}

// ---------------- K4: out = attn @ V then 16x16 projection ------------------
#define OAPITCH 32
#define SMEM4 ((MCH * OAPITCH) * 4 + (NCH * 32) * 8 + 256 * 4)

__global__ void __launch_bounds__(256, 2)
k4_out(const float* __restrict__ wproj, float* __restrict__ out) {
    extern __shared__ float sm4[];
    float* oa = sm4;                                  // [496][32]
    float2* attn2 = (float2*)(sm4 + MCH * OAPITCH);   // [31][32] dup pairs
    float* wp_s = sm4 + MCH * OAPITCH + NCH * 32 * 2; // [256]

    const int tid = threadIdx.x;
    const int b = blockIdx.y;
    const int hw0 = blockIdx.x * 32;

    for (int i = tid; i < NCH * NCH; i += 256) {
        int c1 = i / NCH, dc = i - c1 * NCH;
        float a = g_attn[b * NCH * NCH + i];
        attn2[c1 * 32 + dc] = make_float2(a, a);
    }
    wp_s[tid] = wproj[tid];
    __syncthreads();

    // ---- stage 1: oa[16c+r][px] = sum_dc attn[c][dc] * v[16dc+r][px]
    {
        const int pxp = tid & 15, r = tid >> 4;
        const float* vbase = g_v + ((size_t)(b * MCH) + r) * HWSZ + hw0 + 2 * pxp;
        u64 acc[31];
#pragma unroll
        for (int c = 0; c < 31; c++) acc[c] = 0ULL;

        u64 v0 = *(const u64*)(vbase);
        u64 v1 = *(const u64*)(vbase + 16 * HWSZ);
        for (int j = 0; j < 15; j++) {
            int dc = 2 * j;
            u64 n0 = 0ULL, n1 = 0ULL;
            if (j < 14) {
                n0 = *(const u64*)(vbase + (size_t)16 * (dc + 2) * HWSZ);
                n1 = *(const u64*)(vbase + (size_t)16 * (dc + 3) * HWSZ);
            } else {
                n0 = *(const u64*)(vbase + (size_t)16 * 30 * HWSZ);
            }
#pragma unroll
            for (int c = 0; c < 31; c++) {
                ulonglong2 at = *(const ulonglong2*)&attn2[c * 32 + dc];
                fma2(acc[c], v0, at.x);
                fma2(acc[c], v1, at.y);
            }
            v0 = n0; v1 = n1;
        }
#pragma unroll
        for (int c = 0; c < 31; c++) {
            u64 a30 = *(const u64*)&attn2[c * 32 + 30];
            fma2(acc[c], v0, a30);
        }
#pragma unroll
        for (int c = 0; c < 31; c++)
            *(u64*)&oa[(16 * c + r) * OAPITCH + 2 * pxp] = acc[c];
    }
    __syncthreads();

    // ---- stage 2: out[o*31+ds][px] = sum_i wp[o][i] * oa[i*31+ds][px]
    {
        const int pxp = tid & 15;
        const int oo = (tid >> 4) & 7;
        const int dsg = tid >> 7;
        const int o0 = 2 * oo, o1 = 2 * oo + 1;
        u64 wpa[16], wpb[16];
#pragma unroll
        for (int i = 0; i < 16; i++) {
            float wa = wp_s[o0 * 16 + i], wb = wp_s[o1 * 16 + i];
            wpa[i] = pack2(wa, wa);
            wpb[i] = pack2(wb, wb);
        }
        for (int ds = dsg; ds < NCH; ds += 2) {
            u64 a0 = 0ULL, a1 = 0ULL;
#pragma unroll
            for (int i = 0; i < 16; i++) {
                u64 ov = *(const u64*)&oa[(i * NCH + ds) * OAPITCH + 2 * pxp];
                fma2(a0, ov, wpa[i]);
                fma2(a1, ov, wpb[i]);
            }
            size_t obase = ((size_t)((b * 16 + o0) * DD + ds)) * HWSZ + hw0 + 2 * pxp;
            *(u64*)&out[obase] = a0;
            *(u64*)&out[obase + (size_t)DD * HWSZ] = a1;
        }
    }
}

// ---------------- launch -----------------------------------------------------
extern "C" void kernel_launch(void* const* d_in, const int* in_sizes, int n_in,
                              void* d_out, int out_size) {
    const float* x     = (const float*)d_in[0];
    const float* wqkv  = (const float*)d_in[1];
    const float* wdw   = (const float*)d_in[2];
    const float* wproj = (const float*)d_in[3];
    const float* temp  = (const float*)d_in[4];
    float* out = (float*)d_out;

    cudaFuncSetAttribute(k2_gram, cudaFuncAttributeMaxDynamicSharedMemorySize, SMEM2);
    cudaFuncSetAttribute(k4_out,  cudaFuncAttributeMaxDynamicSharedMemorySize, SMEM4);

    k0_zero<<<16, 256>>>();

    dim3 g1(32, BB * DD);
    k1_qkv<<<g1, 256>>>(x, wqkv, wdw);

    dim3 g2(64, BB);
    k2_gram<<<g2, 256, SMEM2>>>();

    dim3 g3(NCH, BB);
    k3_softmax<<<g3, 32>>>(temp);

    dim3 g4(HWSZ / 32, BB);
    k4_out<<<g4, 256, SMEM4>>>(wproj, out);
}